// round 5
// baseline (speedup 1.0000x reference)
#include <cuda_runtime.h>

#define BB 4
#define CC 256
#define HH 64
#define WW 96
#define ND 21
#define HW (HH * WW)
#define CSTRIDE (4 * HW)     // 4 channels per chunk

// per-buffer geometry (float units); quad = 4 floats = 4 channels at one position
#define S2D 276              // V row pitch: 69 quads (69 % 8 == 5, odd -> l-distinct banks)
#define S2B 2208             // 8 V rows
#define SM1 2208             // A offset inside buffer
#define S1R 192              // A row pitch: 48 quads
#define BUFSZ 2592           // floats per buffer (V + 2 A rows)
#define NBUF 4

__device__ __forceinline__ void fma2(unsigned long long& acc,
                                     unsigned long long a, unsigned long long b) {
    asm("fma.rn.f32x2 %0, %1, %2, %0;" : "+l"(acc) : "l"(a), "l"(b));
}
__device__ __forceinline__ float pairsum(unsigned long long v) {
    float lo, hi;
    asm("mov.b64 {%0, %1}, %2;" : "=f"(lo), "=f"(hi) : "l"(v));
    return lo + hi;
}

// Grid: (dyg in [0,3), yp in [0,32), bp in [0,8): b=bp>>1, parity=bp&1). 768 blocks.
// Block: 288 thr: l=tid&7 (V row), g=(tid>>3)%12 (4-half pixel group), dxg=(tid>>3)/12.
// Thread: pixels x=2(4g+kk)+p (kk<4), dx=7dxg+j (j<7), rows y0 and y0+2 share V row l.
// acc: 56 f32x2 (channel-even/odd partials). Positions pos=4g+7dxg+(kk+j), t=kk+j<10.
__global__ __launch_bounds__(288, 1)
void corr_kernel(const float* __restrict__ in1, const float* __restrict__ in2,
                 float* __restrict__ out) {
    const int dyg = blockIdx.x;
    const int yp  = blockIdx.y;
    const int b   = blockIdx.z >> 1;
    const int p   = blockIdx.z & 1;
    const int y0  = 4 * (yp >> 1) + (yp & 1);

    __shared__ __align__(16) float SM[NBUF * BUFSZ];

    const int tid = threadIdx.x;
    for (int i = tid; i < NBUF * BUFSZ; i += 288) SM[i] = 0.f;   // OOB/halo stay zero

    // ---- staging roles: 240 threads x 2 quads = 480 quads (384 V + 96 A) per chunk
    const float* gp[2];
    int so[2];
    if (tid < 240) {
#pragma unroll
        for (int s = 0; s < 2; s++) {
            int pidx = tid + 240 * s;
            if (pidx < 384) {                       // V: row m, interior pos u = u10+10
                int m   = pidx / 48;
                int u10 = pidx - 48 * m;
                int yy  = y0 + 14 * dyg + 2 * m - 20;
                bool v  = ((unsigned)yy < (unsigned)HH);
                gp[s] = in2 + ((size_t)b * CC) * HW + yy * WW + (p + 2 * u10);
                so[s] = v ? (m * S2D + 4 * (u10 + 10)) : -1;
            } else {                                // A: row yr, half h
                int rem = pidx - 384;
                int yr  = rem / 48;
                int h   = rem - 48 * yr;
                gp[s] = in1 + ((size_t)b * CC) * HW + (y0 + 2 * yr) * WW + (2 * h + p);
                so[s] = SM1 + yr * S1R + 4 * h;
            }
        }
    } else {
        gp[0] = gp[1] = in1; so[0] = so[1] = -1;
    }

    // ---- compute roles ----
    const int l    = tid & 7;
    const int rest = tid >> 3;
    const int g    = rest % 12;
    const int dxg  = rest / 12;
    const int pos0 = 4 * g + 7 * dxg;

    float4 pf[2];
    auto do_ldg = [&]() {
#pragma unroll
        for (int s = 0; s < 2; s++) {
            if (so[s] >= 0) {
                const float* q = gp[s];
                pf[s] = make_float4(q[0], q[HW], q[2 * HW], q[3 * HW]);
            }
            gp[s] += CSTRIDE;
        }
    };
    auto do_sts = [&](int bsel) {
        float* base = SM + bsel * BUFSZ;
#pragma unroll
        for (int s = 0; s < 2; s++)
            if (so[s] >= 0) *(float4*)(base + so[s]) = pf[s];
    };

    unsigned long long accY[28], accZ[28];
#pragma unroll
    for (int i = 0; i < 28; i++) { accY[i] = 0ull; accZ[i] = 0ull; }

    auto compute = [&](int k) {
        const float* buf = SM + (k & 3) * BUFSZ;
        const ulonglong2* Vr = (const ulonglong2*)(buf + l * S2D) + pos0;
        const ulonglong2* Ar = (const ulonglong2*)(buf + SM1) + 4 * g;
        ulonglong2 Ay[4], Az[4];
#pragma unroll
        for (int kk = 0; kk < 4; kk++) { Ay[kk] = Ar[kk]; Az[kk] = Ar[48 + kk]; }
#pragma unroll
        for (int t = 0; t < 10; t++) {
            ulonglong2 V = Vr[t];
            const int klo = (t > 6) ? (t - 6) : 0;
            const int khi = (t < 3) ? t : 3;
#pragma unroll
            for (int kk = klo; kk <= khi; kk++) {
                const int idx = (t - kk) * 4 + kk;   // j*4+kk
                fma2(accY[idx], Ay[kk].x, V.x);
                fma2(accY[idx], Ay[kk].y, V.y);
                fma2(accZ[idx], Az[kk].x, V.x);
                fma2(accZ[idx], Az[kk].y, V.y);
            }
        }
    };

    __syncthreads();                 // zeroing done before first STS
    do_ldg(); do_sts(0);
    do_ldg(); do_sts(1);
    __syncthreads();

#pragma unroll 1
    for (int k = 0; k < 64; k += 2) {
        const bool pre = (k + 2 < 64);
        if (pre) do_ldg();
        compute(k);
        if (pre) do_sts((k + 2) & 3);
        if (pre) do_ldg();
        compute(k + 1);
        if (pre) do_sts((k + 3) & 3);
        __syncthreads();
    }

    // ---- epilogue ----
    const float scale = 1.f / 256.f;
    const int xb = 8 * g + p;
    if (l <= 6) {                    // row y0, dy index 7dyg+l
        int dyi = 7 * dyg + l;
        for (int j = 0; j < 7; j++) {
            int d = dyi * ND + 7 * dxg + j;
            float* op = out + (((size_t)b * ND * ND + d) * HH + y0) * WW + xb;
#pragma unroll
            for (int kk = 0; kk < 4; kk++)
                op[2 * kk] = pairsum(accY[j * 4 + kk]) * scale;
        }
    }
    if (l >= 1) {                    // row y0+2, dy index 7dyg+l-1
        int dyi = 7 * dyg + l - 1;
        for (int j = 0; j < 7; j++) {
            int d = dyi * ND + 7 * dxg + j;
            float* op = out + (((size_t)b * ND * ND + d) * HH + (y0 + 2)) * WW + xb;
#pragma unroll
            for (int kk = 0; kk < 4; kk++)
                op[2 * kk] = pairsum(accZ[j * 4 + kk]) * scale;
        }
    }
}

extern "C" void kernel_launch(void* const* d_in, const int* in_sizes, int n_in,
                              void* d_out, int out_size) {
    const float* in1 = (const float*)d_in[0];
    const float* in2 = (const float*)d_in[1];
    float* out = (float*)d_out;
    dim3 grid(3, 32, 8);
    corr_kernel<<<grid, 288>>>(in1, in2, out);
}

// round 6
// speedup vs baseline: 1.1611x; 1.1611x over previous
#include <cuda_runtime.h>

#define BB 4
#define CC 256
#define HH 64
#define WW 96
#define ND 21
#define HW (HH * WW)
#define CSTRIDE (4 * HW)     // 4 channels per chunk

// per-buffer geometry (float units); quad = 4 floats = 4 channels at one position
#define S2D 276              // V row pitch: 69 quads (69 % 8 == 5, odd -> l-distinct banks)
#define S2B 2208             // 8 V rows
#define SM1 2208             // A offset inside buffer
#define S1R 192              // A row pitch: 48 quads
#define BUFSZ 2592           // floats per buffer
#define NBUF 4

// Grid: (dyg in [0,3), yp in [0,32), bz in [0,8): b=bz>>1, parity p=bz&1). 768 blocks.
// Block: 288 thr, 2 blocks/SM. l=tid&7 (V row), g=(tid>>3)%12, dxg=(tid>>3)/12.
// Thread: 4 pixels x=8g+2kk+p (kk<4), 7 dx=7dxg+j, rows y0 and y0+2 share V row l:
//   row y0   -> dyi = 7dyg+l   (l<=6)
//   row y0+2 -> dyi = 7dyg+l-1 (l>=1)
// V half-index u = 4g+kk+7dxg+j-10 stored at pos u+10 -> pos = 4g+7dxg+(kk+j), t=kk+j<10.
// Conflict-free: V quad idx mod 8 = 5l + const over an 8-lane phase; A is broadcast.
__global__ __launch_bounds__(288, 2)
void corr_kernel(const float* __restrict__ in1, const float* __restrict__ in2,
                 float* __restrict__ out) {
    const int dyg = blockIdx.x;
    const int yp  = blockIdx.y;
    const int b   = blockIdx.z >> 1;
    const int p   = blockIdx.z & 1;
    const int y0  = 4 * (yp >> 1) + (yp & 1);

    __shared__ __align__(16) float SM[NBUF * BUFSZ];

    const int tid = threadIdx.x;
    for (int i = tid; i < NBUF * BUFSZ; i += 288) SM[i] = 0.f;   // halo/OOB stay zero

    // ---- staging: 240 threads x 2 quads = 480 quads (384 V + 96 A) per chunk
    const float* gp[2];
    int so[2];
    if (tid < 240) {
#pragma unroll
        for (int s = 0; s < 2; s++) {
            int pidx = tid + 240 * s;
            if (pidx < 384) {                       // V: row m, interior half u10
                int m   = pidx / 48;
                int u10 = pidx - 48 * m;
                int yy  = y0 + 14 * dyg + 2 * m - 20;
                bool v  = ((unsigned)yy < (unsigned)HH);
                gp[s] = in2 + ((size_t)b * CC) * HW + yy * WW + (p + 2 * u10);
                so[s] = v ? (m * S2D + 4 * (u10 + 10)) : -1;
            } else {                                // A: row yr (y0 or y0+2), half h
                int rem = pidx - 384;
                int yr  = rem / 48;
                int h   = rem - 48 * yr;
                gp[s] = in1 + ((size_t)b * CC) * HW + (y0 + 2 * yr) * WW + (2 * h + p);
                so[s] = SM1 + yr * S1R + 4 * h;
            }
        }
    } else {
        gp[0] = gp[1] = in1; so[0] = so[1] = -1;
    }

    // ---- compute roles ----
    const int l    = tid & 7;
    const int rest = tid >> 3;
    const int g    = rest % 12;
    const int dxg  = rest / 12;
    const int pos0 = 4 * g + 7 * dxg;

    float4 pf[2];
    auto do_ldg = [&]() {
#pragma unroll
        for (int s = 0; s < 2; s++) {
            if (so[s] >= 0) {
                const float* q = gp[s];
                pf[s] = make_float4(q[0], q[HW], q[2 * HW], q[3 * HW]);
            }
            gp[s] += CSTRIDE;
        }
    };
    auto do_sts = [&](int bsel) {
        float* base = SM + bsel * BUFSZ;
#pragma unroll
        for (int s = 0; s < 2; s++)
            if (so[s] >= 0) *(float4*)(base + so[s]) = pf[s];
    };

    float accY[28], accZ[28];                       // [j*4+kk], rows y0 / y0+2
#pragma unroll
    for (int i = 0; i < 28; i++) { accY[i] = 0.f; accZ[i] = 0.f; }

    auto compute = [&](int k) {
        const float* buf = SM + (k & 3) * BUFSZ;
        const float4* Vr = (const float4*)(buf + l * S2D) + pos0;
        const float4* Ar = (const float4*)(buf + SM1) + 4 * g;
        float4 Ay[4], Az[4];
#pragma unroll
        for (int kk = 0; kk < 4; kk++) { Ay[kk] = Ar[kk]; Az[kk] = Ar[48 + kk]; }
#pragma unroll
        for (int t = 0; t < 10; t++) {
            float4 V = Vr[t];
            const int klo = (t > 6) ? (t - 6) : 0;
            const int khi = (t < 3) ? t : 3;
#pragma unroll
            for (int kk = klo; kk <= khi; kk++) {
                const int idx = (t - kk) * 4 + kk;  // j*4+kk
                float ty = accY[idx];
                ty = fmaf(Ay[kk].x, V.x, ty); ty = fmaf(Ay[kk].y, V.y, ty);
                ty = fmaf(Ay[kk].z, V.z, ty); ty = fmaf(Ay[kk].w, V.w, ty);
                accY[idx] = ty;
                float tz = accZ[idx];
                tz = fmaf(Az[kk].x, V.x, tz); tz = fmaf(Az[kk].y, V.y, tz);
                tz = fmaf(Az[kk].z, V.z, tz); tz = fmaf(Az[kk].w, V.w, tz);
                accZ[idx] = tz;
            }
        }
    };

    __syncthreads();                 // zeroing done before first STS
    do_ldg(); do_sts(0);
    do_ldg(); do_sts(1);
    __syncthreads();

#pragma unroll 1
    for (int k = 0; k < 64; k += 2) {
        const bool pre = (k + 2 < 64);
        if (pre) do_ldg();
        compute(k);
        if (pre) do_sts((k + 2) & 3);
        if (pre) do_ldg();
        compute(k + 1);
        if (pre) do_sts((k + 3) & 3);
        __syncthreads();
    }

    // ---- epilogue ----
    const float scale = 1.f / 256.f;
    const int xb = 8 * g + p;
    if (l <= 6) {                    // row y0
        int dyi = 7 * dyg + l;
        for (int j = 0; j < 7; j++) {
            int d = dyi * ND + 7 * dxg + j;
            float* op = out + (((size_t)b * ND * ND + d) * HH + y0) * WW + xb;
#pragma unroll
            for (int kk = 0; kk < 4; kk++)
                op[2 * kk] = accY[j * 4 + kk] * scale;
        }
    }
    if (l >= 1) {                    // row y0+2
        int dyi = 7 * dyg + l - 1;
        for (int j = 0; j < 7; j++) {
            int d = dyi * ND + 7 * dxg + j;
            float* op = out + (((size_t)b * ND * ND + d) * HH + (y0 + 2)) * WW + xb;
#pragma unroll
            for (int kk = 0; kk < 4; kk++)
                op[2 * kk] = accZ[j * 4 + kk] * scale;
        }
    }
}

extern "C" void kernel_launch(void* const* d_in, const int* in_sizes, int n_in,
                              void* d_out, int out_size) {
    const float* in1 = (const float*)d_in[0];
    const float* in2 = (const float*)d_in[1];
    float* out = (float*)d_out;
    dim3 grid(3, 32, 8);
    corr_kernel<<<grid, 288>>>(in1, in2, out);
}

// round 7
// speedup vs baseline: 1.1626x; 1.0012x over previous
#include <cuda_runtime.h>

#define BB 4
#define CC 256
#define HH 64
#define WW 96
#define ND 21
#define HW (HH * WW)
#define CSTRIDE (4 * HW)     // 4 channels per chunk

// per-buffer geometry (float units); quad = 4 floats = 4 channels at one position
#define S2D 276              // V row pitch: 69 quads (69 % 8 == 5, odd -> l-distinct banks)
#define S2B 2208             // 8 V rows
#define SM1 2208             // A offset inside buffer
#define S1R 192              // A row pitch: 48 quads
#define BUFSZ 2592           // floats per buffer
#define NBUF 4

// Grid: (dyg in [0,3), yp in [0,32), bz in [0,8): b=bz>>1, parity p=bz&1). 768 blocks.
// Block: 288 thr, 2 blocks/SM. l=tid&7 (V row), g=(tid>>3)%12, dxg=(tid>>3)/12.
// Thread: 4 pixels x=8g+2kk+p (kk<4), 7 dx=7dxg+j, rows y0 and y0+2 share V row l:
//   row y0   -> dyi = 7dyg+l   (l<=6)
//   row y0+2 -> dyi = 7dyg+l-1 (l>=1)
// V half-index u = 4g+kk+7dxg+j-10 stored at pos u+10 -> pos = 4g+7dxg+(kk+j), t=kk+j<10.
// Conflict-free: V quad idx mod 8 = 5l + const over an 8-lane phase; A is broadcast.
__global__ __launch_bounds__(288, 2)
void corr_kernel(const float* __restrict__ in1, const float* __restrict__ in2,
                 float* __restrict__ out) {
    const int dyg = blockIdx.x;
    const int yp  = blockIdx.y;
    const int b   = blockIdx.z >> 1;
    const int p   = blockIdx.z & 1;
    const int y0  = 4 * (yp >> 1) + (yp & 1);

    __shared__ __align__(16) float SM[NBUF * BUFSZ];

    const int tid = threadIdx.x;
    for (int i = tid; i < NBUF * BUFSZ; i += 288) SM[i] = 0.f;   // halo/OOB stay zero

    // ---- staging: 240 threads x 2 quads = 480 quads (384 V + 96 A) per chunk
    const float* gp[2];
    int so[2];
    if (tid < 240) {
#pragma unroll
        for (int s = 0; s < 2; s++) {
            int pidx = tid + 240 * s;
            if (pidx < 384) {                       // V: row m, interior half u10
                int m   = pidx / 48;
                int u10 = pidx - 48 * m;
                int yy  = y0 + 14 * dyg + 2 * m - 20;
                bool v  = ((unsigned)yy < (unsigned)HH);
                gp[s] = in2 + ((size_t)b * CC) * HW + yy * WW + (p + 2 * u10);
                so[s] = v ? (m * S2D + 4 * (u10 + 10)) : -1;
            } else {                                // A: row yr (y0 or y0+2), half h
                int rem = pidx - 384;
                int yr  = rem / 48;
                int h   = rem - 48 * yr;
                gp[s] = in1 + ((size_t)b * CC) * HW + (y0 + 2 * yr) * WW + (2 * h + p);
                so[s] = SM1 + yr * S1R + 4 * h;
            }
        }
    } else {
        gp[0] = gp[1] = in1; so[0] = so[1] = -1;
    }

    // ---- compute roles ----
    const int l    = tid & 7;
    const int rest = tid >> 3;
    const int g    = rest % 12;
    const int dxg  = rest / 12;
    const int pos0 = 4 * g + 7 * dxg;

    float4 pf[2];
    auto do_ldg = [&]() {
#pragma unroll
        for (int s = 0; s < 2; s++) {
            if (so[s] >= 0) {
                const float* q = gp[s];
                pf[s] = make_float4(q[0], q[HW], q[2 * HW], q[3 * HW]);
            }
            gp[s] += CSTRIDE;
        }
    };
    auto do_sts = [&](int bsel) {
        float* base = SM + bsel * BUFSZ;
#pragma unroll
        for (int s = 0; s < 2; s++)
            if (so[s] >= 0) *(float4*)(base + so[s]) = pf[s];
    };

    float accY[28], accZ[28];                       // [j*4+kk], rows y0 / y0+2
#pragma unroll
    for (int i = 0; i < 28; i++) { accY[i] = 0.f; accZ[i] = 0.f; }

    auto compute = [&](int k) {
        const float* buf = SM + (k & 3) * BUFSZ;
        const float4* Vr = (const float4*)(buf + l * S2D) + pos0;
        const float4* Ar = (const float4*)(buf + SM1) + 4 * g;
        float4 Ay[4], Az[4];
#pragma unroll
        for (int kk = 0; kk < 4; kk++) { Ay[kk] = Ar[kk]; Az[kk] = Ar[48 + kk]; }
#pragma unroll
        for (int t = 0; t < 10; t++) {
            float4 V = Vr[t];
            const int klo = (t > 6) ? (t - 6) : 0;
            const int khi = (t < 3) ? t : 3;
#pragma unroll
            for (int kk = klo; kk <= khi; kk++) {
                const int idx = (t - kk) * 4 + kk;  // j*4+kk
                float ty = accY[idx];
                ty = fmaf(Ay[kk].x, V.x, ty); ty = fmaf(Ay[kk].y, V.y, ty);
                ty = fmaf(Ay[kk].z, V.z, ty); ty = fmaf(Ay[kk].w, V.w, ty);
                accY[idx] = ty;
                float tz = accZ[idx];
                tz = fmaf(Az[kk].x, V.x, tz); tz = fmaf(Az[kk].y, V.y, tz);
                tz = fmaf(Az[kk].z, V.z, tz); tz = fmaf(Az[kk].w, V.w, tz);
                accZ[idx] = tz;
            }
        }
    };

    __syncthreads();                 // zeroing done before first STS
    do_ldg(); do_sts(0);
    do_ldg(); do_sts(1);
    __syncthreads();

#pragma unroll 1
    for (int k = 0; k < 64; k += 2) {
        const bool pre = (k + 2 < 64);
        if (pre) do_ldg();
        compute(k);
        if (pre) do_sts((k + 2) & 3);
        if (pre) do_ldg();
        compute(k + 1);
        if (pre) do_sts((k + 3) & 3);
        __syncthreads();
    }

    // ---- epilogue ----
    const float scale = 1.f / 256.f;
    const int xb = 8 * g + p;
    if (l <= 6) {                    // row y0
        int dyi = 7 * dyg + l;
        for (int j = 0; j < 7; j++) {
            int d = dyi * ND + 7 * dxg + j;
            float* op = out + (((size_t)b * ND * ND + d) * HH + y0) * WW + xb;
#pragma unroll
            for (int kk = 0; kk < 4; kk++)
                op[2 * kk] = accY[j * 4 + kk] * scale;
        }
    }
    if (l >= 1) {                    // row y0+2
        int dyi = 7 * dyg + l - 1;
        for (int j = 0; j < 7; j++) {
            int d = dyi * ND + 7 * dxg + j;
            float* op = out + (((size_t)b * ND * ND + d) * HH + (y0 + 2)) * WW + xb;
#pragma unroll
            for (int kk = 0; kk < 4; kk++)
                op[2 * kk] = accZ[j * 4 + kk] * scale;
        }
    }
}

extern "C" void kernel_launch(void* const* d_in, const int* in_sizes, int n_in,
                              void* d_out, int out_size) {
    const float* in1 = (const float*)d_in[0];
    const float* in2 = (const float*)d_in[1];
    float* out = (float*)d_out;
    dim3 grid(3, 32, 8);
    corr_kernel<<<grid, 288>>>(in1, in2, out);
}

// round 11
// speedup vs baseline: 1.3667x; 1.1756x over previous
#include <cuda_runtime.h>
#include <cstdint>

#define BB 4
#define CC 256
#define HH 64
#define WW 96
#define ND 21
#define HW (HH * WW)
#define CSTRIDE (4 * HW)     // advance 4 channels per chunk

// per-buffer geometry (float units); quad = 4 floats = 4 channels at one half-position
#define S2D 276              // V row pitch: 69 quads (69 % 8 == 5 -> 8-lane phases conflict-free)
#define SM1 2208             // A offset inside buffer (after 8 V rows)
#define S1R 192              // A row pitch: 48 quads
#define BUFSZ 2592           // floats per buffer
#define NBUF 4

static __device__ __forceinline__ void fma2(unsigned long long& acc,
                                            unsigned long long a, unsigned long long b) {
    asm("fma.rn.f32x2 %0, %1, %2, %0;" : "+l"(acc) : "l"(a), "l"(b));
}
static __device__ __forceinline__ float pairsum(unsigned long long v) {
    float lo, hi;
    asm("mov.b64 {%0, %1}, %2;" : "=f"(lo), "=f"(hi) : "l"(v));
    return lo + hi;
}

// Grid: (dyg in [0,3), yp in [0,32), bz: b=bz>>1, parity p=bz&1). 768 blocks, 1 CTA/SM.
// Block 576 thr: l=tid&7 (V row), rest=tid>>3: g=rest%24 (2-half pixel group), dxg=rest/24.
// Thread: 2 pixels x=2(2g+kk)+p (kk<2), 7 dx=7dxg+j, rows y0 / y0+2 share V row l:
//   row y0   -> dyi = 7dyg+l   (valid l<=6);  row y0+2 -> dyi = 7dyg+l-1 (valid l>=1)
// V position pos = 2g+7dxg + (kk+j) = pos0 + t, t in [0,8). acc pair = (even-ch, odd-ch).
__global__ __launch_bounds__(576, 1)
void corr_kernel(const float* __restrict__ in1, const float* __restrict__ in2,
                 float* __restrict__ out) {
    const int dyg = blockIdx.x;
    const int yp  = blockIdx.y;
    const int b   = blockIdx.z >> 1;
    const int p   = blockIdx.z & 1;
    const int y0  = 4 * (yp >> 1) + (yp & 1);

    __shared__ __align__(16) float SM[NBUF * BUFSZ];   // 41472 B, static

    const int tid = threadIdx.x;
    for (int i = tid; i < NBUF * BUFSZ; i += 576) SM[i] = 0.f;   // halo/OOB stay zero

    // ---- staging: threads 0..479 load ONE channel-quad each (384 V + 96 A)
    const float* gp = in1;
    int so = -1;
    if (tid < 480) {
        if (tid < 384) {                        // V: row m, interior half u10
            int m   = tid / 48;
            int u10 = tid - 48 * m;
            int yy  = y0 + 14 * dyg + 2 * m - 20;
            bool v  = ((unsigned)yy < (unsigned)HH);
            gp = in2 + ((size_t)b * CC) * HW + (v ? yy : 0) * WW + (p + 2 * u10);
            so = v ? (m * S2D + 4 * (u10 + 10)) : -1;
        } else {                                // A: row yr (y0 or y0+2), half h
            int rem = tid - 384;
            int yr  = rem / 48;
            int h   = rem - 48 * yr;
            gp = in1 + ((size_t)b * CC) * HW + (y0 + 2 * yr) * WW + (2 * h + p);
            so = SM1 + yr * S1R + 4 * h;
        }
    }

    // ---- compute roles ----
    const int l    = tid & 7;
    const int rest = tid >> 3;
    const int g    = rest % 24;
    const int dxg  = rest / 24;
    const int pos0 = 2 * g + 7 * dxg;           // 0..60

    float4 pf;
    auto do_ldg = [&]() {
        if (so >= 0) pf = make_float4(gp[0], gp[HW], gp[2 * HW], gp[3 * HW]);
        gp += CSTRIDE;
    };
    auto do_sts = [&](int bsel) {
        if (so >= 0) *(float4*)(SM + bsel * BUFSZ + so) = pf;
    };

    unsigned long long aY[14], aZ[14];          // [j*2+kk]
#pragma unroll
    for (int i = 0; i < 14; i++) { aY[i] = 0ull; aZ[i] = 0ull; }

    auto compute = [&](int k) {
        const float* buf = SM + (k & 3) * BUFSZ;
        const ulonglong2* Vq = (const ulonglong2*)(buf + l * S2D) + pos0;
        const ulonglong2* Aq = (const ulonglong2*)(buf + SM1) + 2 * g;
        const ulonglong2 Ay0 = Aq[0], Ay1 = Aq[1];       // row y0,  kk=0/1
        const ulonglong2 Az0 = Aq[48], Az1 = Aq[49];     // row y0+2
#pragma unroll
        for (int t = 0; t < 8; t++) {
            ulonglong2 V = Vq[t];
            if (t <= 6) {                       // kk = 0, j = t
                const int idx = 2 * t;
                fma2(aY[idx], Ay0.x, V.x); fma2(aY[idx], Ay0.y, V.y);
                fma2(aZ[idx], Az0.x, V.x); fma2(aZ[idx], Az0.y, V.y);
            }
            if (t >= 1) {                       // kk = 1, j = t-1
                const int idx = 2 * (t - 1) + 1;
                fma2(aY[idx], Ay1.x, V.x); fma2(aY[idx], Ay1.y, V.y);
                fma2(aZ[idx], Az1.x, V.x); fma2(aZ[idx], Az1.y, V.y);
            }
        }
    };

    __syncthreads();                 // zeroing complete before first STS
    do_ldg(); do_sts(0);
    do_ldg(); do_sts(1);
    __syncthreads();

#pragma unroll 1
    for (int k = 0; k < 64; k += 2) {
        const bool pre = (k + 2 < 64);
        if (pre) do_ldg();
        compute(k);
        if (pre) do_sts((k + 2) & 3);
        if (pre) do_ldg();
        compute(k + 1);
        if (pre) do_sts((k + 3) & 3);
        __syncthreads();
    }

    // ---- epilogue ----
    const float scale = 1.f / 256.f;
    if (l <= 6) {                    // row y0, dyi = 7dyg+l
        const int dyi = 7 * dyg + l;
        for (int j = 0; j < 7; j++) {
            const int d = dyi * ND + 7 * dxg + j;
            float* op = out + (((size_t)b * ND * ND + d) * HH + y0) * WW + (4 * g + p);
            op[0] = pairsum(aY[2 * j]) * scale;
            op[2] = pairsum(aY[2 * j + 1]) * scale;
        }
    }
    if (l >= 1) {                    // row y0+2, dyi = 7dyg+l-1
        const int dyi = 7 * dyg + l - 1;
        for (int j = 0; j < 7; j++) {
            const int d = dyi * ND + 7 * dxg + j;
            float* op = out + (((size_t)b * ND * ND + d) * HH + (y0 + 2)) * WW + (4 * g + p);
            op[0] = pairsum(aZ[2 * j]) * scale;
            op[2] = pairsum(aZ[2 * j + 1]) * scale;
        }
    }
}

extern "C" void kernel_launch(void* const* d_in, const int* in_sizes, int n_in,
                              void* d_out, int out_size) {
    const float* in1 = (const float*)d_in[0];
    const float* in2 = (const float*)d_in[1];
    float* out = (float*)d_out;
    dim3 grid(3, 32, 8);
    corr_kernel<<<grid, 576>>>(in1, in2, out);
}